// round 3
// baseline (speedup 1.0000x reference)
#include <cuda_runtime.h>
#include <math_constants.h>

// AutoCorrelation (Autoformer): q,k,v (32,8,2048,64) fp32.
// corr[r,d] = sum_j q[r,j]*k[r,(j-d)%64]; top-4 over d, softmax, gather v.
// out = [ V (B,H,L,E) | corr^T (B,E,H,L) ]
//
// One thread = TWO rows (rA = r0+lane, rB = rA+32). The shift index
// (j-d)&63 is row-independent, so k for both rows packs into 64 b64 regs
// and the correlation runs on fma.rn.f32x2 (FFMA2) — 2 rows per instr.

#define STR 65            // smem row stride in floats (odd -> conflict-free)
#define TOPK 4

#define FMA2(c, a, b) \
    asm("fma.rn.f32x2 %0, %1, %2, %0;" : "+l"(c) : "l"(a), "l"(b))
#define PACK2(d, lo, hi) \
    asm("mov.b64 %0, {%1, %2};" : "=l"(d) : "f"(lo), "f"(hi))
#define UNPACK2(lo, hi, d) \
    asm("mov.b64 {%0, %1}, %2;" : "=f"(lo), "=f"(hi) : "l"(d))

__global__ void __launch_bounds__(64, 5)
autocorr_kernel(const float* __restrict__ gq,
                const float* __restrict__ gk,
                const float* __restrict__ gv,
                float* __restrict__ outV,
                float* __restrict__ outC) {
    __shared__ float tile[2][64][STR];          // one 64-row tile per warp

    const int w    = threadIdx.x >> 5;
    const int lane = threadIdx.x & 31;
    float (*T)[STR] = tile[w];

    const long long r0  = ((long long)blockIdx.x * 2 + w) * 64;  // 64 rows/warp
    const long long off = r0 * 64;

    // ---- stage k (coalesced, conflict-free), pack per-thread row pair ----
    #pragma unroll
    for (int it = 0; it < 128; it++) {
        int f = it * 32 + lane;
        T[f >> 6][f & 63] = gk[off + f];
    }
    __syncwarp();
    unsigned long long k2[64];
    #pragma unroll
    for (int j = 0; j < 64; j++) PACK2(k2[j], T[lane][j], T[lane + 32][j]);
    __syncwarp();

    // ---- stage q ----
    #pragma unroll
    for (int it = 0; it < 128; it++) {
        int f = it * 32 + lane;
        T[f >> 6][f & 63] = gq[off + f];
    }
    __syncwarp();

    // ---- top-4 state for both rows ----
    float wA0=-CUDART_INF_F, wA1=-CUDART_INF_F, wA2=-CUDART_INF_F, wA3=-CUDART_INF_F;
    float wB0=-CUDART_INF_F, wB1=-CUDART_INF_F, wB2=-CUDART_INF_F, wB3=-CUDART_INF_F;
    int iA0=0,iA1=0,iA2=0,iA3=0, iB0=0,iB1=0,iB2=0,iB3=0;

    // corr^T addressing: all 64 rows share (b,h); lA = l0+lane, lB = lA+32
    const int b = (int)(r0 >> 14);
    const int h = ((int)(r0 >> 11)) & 7;
    const int l = ((int)(r0 & 2047)) + lane;
    float* cA = outC + (long long)b * (64 * 8 * 2048) + (long long)h * 2048 + l;

    // ---- correlation: 4 passes x 16 packed accumulators, FFMA2 ----
    #pragma unroll
    for (int pass = 0; pass < 4; pass++) {
        unsigned long long c2[16];
        #pragma unroll
        for (int dd = 0; dd < 16; dd++) c2[dd] = 0ull;

        #pragma unroll
        for (int j = 0; j < 64; j++) {
            unsigned long long q2;
            PACK2(q2, T[lane][j], T[lane + 32][j]);
            #pragma unroll
            for (int dd = 0; dd < 16; dd++) {
                FMA2(c2[dd], q2, k2[(j + 64 - pass * 16 - dd) & 63]);
            }
        }

        #pragma unroll
        for (int dd = 0; dd < 16; dd++) {
            const int d = pass * 16 + dd;
            float va, vb;
            UNPACK2(va, vb, c2[dd]);
            cA[(long long)d * 16384]      = va;   // lanes contiguous in l
            cA[(long long)d * 16384 + 32] = vb;
            // strict-> insertion keeps lowest index on ties (lax.top_k)
            if (va > wA3) {
                if (va > wA2) {
                    if (va > wA1) {
                        if (va > wA0) { wA3=wA2;iA3=iA2; wA2=wA1;iA2=iA1; wA1=wA0;iA1=iA0; wA0=va;iA0=d; }
                        else          { wA3=wA2;iA3=iA2; wA2=wA1;iA2=iA1; wA1=va;iA1=d; }
                    } else            { wA3=wA2;iA3=iA2; wA2=va;iA2=d; }
                } else                { wA3=va;iA3=d; }
            }
            if (vb > wB3) {
                if (vb > wB2) {
                    if (vb > wB1) {
                        if (vb > wB0) { wB3=wB2;iB3=iB2; wB2=wB1;iB2=iB1; wB1=wB0;iB1=iB0; wB0=vb;iB0=d; }
                        else          { wB3=wB2;iB3=iB2; wB2=wB1;iB2=iB1; wB1=vb;iB1=d; }
                    } else            { wB3=wB2;iB3=iB2; wB2=vb;iB2=d; }
                } else                { wB3=vb;iB3=d; }
            }
        }
    }

    // ---- softmax weights (w?0 is the max) ----
    float eA1=__expf(wA1-wA0), eA2=__expf(wA2-wA0), eA3=__expf(wA3-wA0);
    float sA = 1.f/(1.f+eA1+eA2+eA3);
    const float tA0=sA, tA1=eA1*sA, tA2=eA2*sA, tA3=eA3*sA;
    float eB1=__expf(wB1-wB0), eB2=__expf(wB2-wB0), eB3=__expf(wB3-wB0);
    float sB = 1.f/(1.f+eB1+eB2+eB3);
    const float tB0=sB, tB1=eB1*sB, tB2=eB2*sB, tB3=eB3*sB;

    // ---- stage v ----
    #pragma unroll
    for (int it = 0; it < 128; it++) {
        int f = it * 32 + lane;
        T[f >> 6][f & 63] = gv[off + f];
    }
    __syncwarp();

    // ---- gather into registers (all reads before any tile writes) ----
    const float* vA = &T[lane][0];
    const float* vB = &T[lane + 32][0];
    float oa[64], ob[64];
    #pragma unroll
    for (int e = 0; e < 64; e++) {
        float sa = tA0 * vA[(e + iA0) & 63];
        sa = fmaf(tA1, vA[(e + iA1) & 63], sa);
        sa = fmaf(tA2, vA[(e + iA2) & 63], sa);
        sa = fmaf(tA3, vA[(e + iA3) & 63], sa);
        oa[e] = sa;
        float sb = tB0 * vB[(e + iB0) & 63];
        sb = fmaf(tB1, vB[(e + iB1) & 63], sb);
        sb = fmaf(tB2, vB[(e + iB2) & 63], sb);
        sb = fmaf(tB3, vB[(e + iB3) & 63], sb);
        ob[e] = sb;
    }
    __syncwarp();
    #pragma unroll
    for (int e = 0; e < 64; e++) {
        T[lane][e]      = oa[e];
        T[lane + 32][e] = ob[e];
    }
    __syncwarp();

    // ---- cooperative coalesced store of V ----
    #pragma unroll
    for (int it = 0; it < 128; it++) {
        int f = it * 32 + lane;
        outV[off + f] = T[f >> 6][f & 63];
    }
}

extern "C" void kernel_launch(void* const* d_in, const int* in_sizes, int n_in,
                              void* d_out, int out_size) {
    const float* q = (const float*)d_in[0];
    const float* k = (const float*)d_in[1];
    const float* v = (const float*)d_in[2];
    float* outV = (float*)d_out;
    float* outC = (float*)d_out + (long long)32 * 8 * 2048 * 64;

    const int rows    = 32 * 8 * 2048;      // 524288
    const int nblocks = rows / (2 * 64);    // 4096 blocks, 2 warps each
    autocorr_kernel<<<nblocks, 64>>>(q, k, v, outV, outC);
}

// round 4
// speedup vs baseline: 1.3170x; 1.3170x over previous
#include <cuda_runtime.h>
#include <math_constants.h>

// AutoCorrelation (Autoformer): q,k,v (32,8,2048,64) fp32.
// corr[r,d] = sum_j q[r,j]*k[r,(j-d)%64]; top-4 over d, softmax, gather v.
// out = [ V (B,H,L,E) | corr^T (B,E,H,L) ]
//
// One thread = TWO rows (rA = R0+lane, rB = rA+32). The shift (j-d)&63 is
// row-independent, so k packs into 64 b64 regs and the correlation runs on
// fma.rn.f32x2 — 2 rows per instruction. q/k/v staged PACKED (float2) in
// smem so the inner loop is 1 LDS.64 + 16 FFMA2 per j.
// launch_bounds(64,4) -> 256-reg budget: no spills (R3 lesson).

#define FMA2(c, a, b) \
    asm("fma.rn.f32x2 %0, %1, %2, %0;" : "+l"(c) : "l"(a), "l"(b))
#define UNPACK2(lo, hi, d) \
    asm("mov.b64 {%0, %1}, %2;" : "=f"(lo), "=f"(hi) : "l"(d))

#define STRP 65   // float2 row stride (padding keeps LDS.64 at the 2-phase floor)

__global__ void __launch_bounds__(64, 4)
autocorr_kernel(const float* __restrict__ gq,
                const float* __restrict__ gk,
                const float* __restrict__ gv,
                float* __restrict__ outV,
                float* __restrict__ outC) {
    __shared__ float2 tile[2][32][STRP];

    const int w    = threadIdx.x >> 5;
    const int lane = threadIdx.x & 31;
    float2 (*T2)[STRP] = tile[w];
    float*  Tf = (float*)&T2[0][0];           // scalar view of this warp's tile

    const long long r0  = ((long long)blockIdx.x * 2 + w) * 64;  // 64 rows/warp
    const long long off = r0 * 64;

    // ---- packed staging: global row r -> T2[r&31][col] component (r>>5) ----
    // it even: rows it/2 cols 0..31 ; it odd: rows it/2 cols 32..63
#define STAGE(gsrc)                                                          \
    _Pragma("unroll")                                                        \
    for (int it = 0; it < 128; it++) {                                       \
        const int r   = it >> 1;                                             \
        const int c0  = (it & 1) << 5;                                       \
        float val = gsrc[off + it * 32 + lane];                              \
        Tf[((r & 31) * STRP + c0 + lane) * 2 + (r >> 5)] = val;              \
    }

    // ---- k: stage packed, pull this thread's row pair into 64 b64 regs ----
    STAGE(gk);
    __syncwarp();
    unsigned long long k2[64];
    #pragma unroll
    for (int j = 0; j < 64; j++)
        k2[j] = *(const unsigned long long*)&T2[lane][j];
    __syncwarp();

    // ---- q: stage packed ----
    STAGE(gq);
    __syncwarp();

    // ---- top-4 state for both rows ----
    float wA0=-CUDART_INF_F, wA1=-CUDART_INF_F, wA2=-CUDART_INF_F, wA3=-CUDART_INF_F;
    float wB0=-CUDART_INF_F, wB1=-CUDART_INF_F, wB2=-CUDART_INF_F, wB3=-CUDART_INF_F;
    int iA0=0,iA1=0,iA2=0,iA3=0, iB0=0,iB1=0,iB2=0,iB3=0;

    // corr^T: all 64 rows share (b,h); lA = l0+lane, lB = lA+32
    const int b = (int)(r0 >> 14);
    const int h = ((int)(r0 >> 11)) & 7;
    const int l = ((int)(r0 & 2047)) + lane;
    float* cA = outC + (long long)b * (64 * 8 * 2048) + (long long)h * 2048 + l;

    // ---- correlation: 4 passes x 16 packed accumulators, FFMA2 ----
    #pragma unroll
    for (int pass = 0; pass < 4; pass++) {
        unsigned long long c2[16];
        #pragma unroll
        for (int dd = 0; dd < 16; dd++) c2[dd] = 0ull;

        #pragma unroll
        for (int j = 0; j < 64; j++) {
            unsigned long long q2 = *(const unsigned long long*)&T2[lane][j];
            #pragma unroll
            for (int dd = 0; dd < 16; dd++)
                FMA2(c2[dd], q2, k2[(j + 64 - pass * 16 - dd) & 63]);
        }

        #pragma unroll
        for (int dd = 0; dd < 16; dd++) {
            const int d = pass * 16 + dd;
            float va, vb;
            UNPACK2(va, vb, c2[dd]);
            cA[d * 16384]      = va;   // lanes contiguous in l -> coalesced
            cA[d * 16384 + 32] = vb;
            // strict-> insertion keeps lowest index on ties (lax.top_k)
            if (va > wA3) {
                if (va > wA2) {
                    if (va > wA1) {
                        if (va > wA0) { wA3=wA2;iA3=iA2; wA2=wA1;iA2=iA1; wA1=wA0;iA1=iA0; wA0=va;iA0=d; }
                        else          { wA3=wA2;iA3=iA2; wA2=wA1;iA2=iA1; wA1=va;iA1=d; }
                    } else            { wA3=wA2;iA3=iA2; wA2=va;iA2=d; }
                } else                { wA3=va;iA3=d; }
            }
            if (vb > wB3) {
                if (vb > wB2) {
                    if (vb > wB1) {
                        if (vb > wB0) { wB3=wB2;iB3=iB2; wB2=wB1;iB2=iB1; wB1=wB0;iB1=iB0; wB0=vb;iB0=d; }
                        else          { wB3=wB2;iB3=iB2; wB2=wB1;iB2=iB1; wB1=vb;iB1=d; }
                    } else            { wB3=wB2;iB3=iB2; wB2=vb;iB2=d; }
                } else                { wB3=vb;iB3=d; }
            }
        }
    }

    // ---- softmax over the 4 weights (w?0 is the max) ----
    float eA1=__expf(wA1-wA0), eA2=__expf(wA2-wA0), eA3=__expf(wA3-wA0);
    float sA = 1.f/(1.f+eA1+eA2+eA3);
    const float tA0=sA, tA1=eA1*sA, tA2=eA2*sA, tA3=eA3*sA;
    float eB1=__expf(wB1-wB0), eB2=__expf(wB2-wB0), eB3=__expf(wB3-wB0);
    float sB = 1.f/(1.f+eB1+eB2+eB3);
    const float tB0=sB, tB1=eB1*sB, tB2=eB2*sB, tB3=eB3*sB;

    // ---- v: stage packed (overwrites q, which is dead) ----
    STAGE(gv);
    __syncwarp();

    // ---- gather + direct V store (4 e per STG.128; L2 merges half-sectors) ----
    {
        const float* vp = (const float*)&T2[lane][0];   // [2m]=rowA, [2m+1]=rowB
        float* outA = outV + off + lane * 64;
        float* outB = outA + 32 * 64;
        #pragma unroll
        for (int eg = 0; eg < 16; eg++) {
            float4 ra, rb;
            #pragma unroll
            for (int s = 0; s < 4; s++) {
                const int e = eg * 4 + s;
                float sa =      tA0 * vp[((e + iA0) & 63) * 2];
                sa = fmaf(tA1, vp[((e + iA1) & 63) * 2], sa);
                sa = fmaf(tA2, vp[((e + iA2) & 63) * 2], sa);
                sa = fmaf(tA3, vp[((e + iA3) & 63) * 2], sa);
                float sb =      tB0 * vp[((e + iB0) & 63) * 2 + 1];
                sb = fmaf(tB1, vp[((e + iB1) & 63) * 2 + 1], sb);
                sb = fmaf(tB2, vp[((e + iB2) & 63) * 2 + 1], sb);
                sb = fmaf(tB3, vp[((e + iB3) & 63) * 2 + 1], sb);
                (&ra.x)[s] = sa;
                (&rb.x)[s] = sb;
            }
            *(float4*)(outA + eg * 4) = ra;
            *(float4*)(outB + eg * 4) = rb;
        }
    }
}

extern "C" void kernel_launch(void* const* d_in, const int* in_sizes, int n_in,
                              void* d_out, int out_size) {
    const float* q = (const float*)d_in[0];
    const float* k = (const float*)d_in[1];
    const float* v = (const float*)d_in[2];
    float* outV = (float*)d_out;
    float* outC = (float*)d_out + (long long)32 * 8 * 2048 * 64;

    const int rows    = 32 * 8 * 2048;      // 524288
    const int nblocks = rows / (2 * 64);    // 4096 blocks, 2 warps each
    autocorr_kernel<<<nblocks, 64>>>(q, k, v, outV, outC);
}

// round 5
// speedup vs baseline: 3.6726x; 2.7887x over previous
#include <cuda_runtime.h>
#include <math_constants.h>

// AutoCorrelation (Autoformer): q,k,v (32,8,2048,64) fp32.
// corr[r,d] = sum_j q[r,j]*k[r,(j-d)%64]; top-4 over d, softmax, gather v.
// out = [ V (B,H,L,E) | corr^T (B,E,H,L) ]
//
// One thread = one row. FFMA2 packs the REDUCTION dim: pairs (j=2m,2m+1).
//   even d=2s:  c2 += q2[m] (*) kE[(m-s)&31],   kE[t]=(k[2t],k[2t+1])   (aligned)
//   odd  d=2s+1: c2 += q2[m] (*) kO[(m-s-1)&31], kO[t]=(k[2t+1],k[2t+2])
// kE and kO are never live together -> ~130 regs, no spill (R3/R4 lesson).

#define FMA2(c, a, b) \
    asm("fma.rn.f32x2 %0, %1, %2, %0;" : "+l"(c) : "l"(a), "l"(b))
#define UNPACK2(lo, hi, d) \
    asm("mov.b64 {%0, %1}, %2;" : "=f"(lo), "=f"(hi) : "l"(d))
#define PACK2(d, lo, hi) \
    asm("mov.b64 %0, {%1, %2};" : "=l"(d) : "f"(lo), "f"(hi))

#define STR2 33   // float2 row stride: bank-pair (33r+m)%32 = (r+m)%32, conflict-free

// topk insert, strict > keeps lowest index on ties (lax.top_k order)
#define TOPK_INS(vv, d)                                                          \
    if (vv > w3) {                                                               \
        if (vv > w2) {                                                           \
            if (vv > w1) {                                                       \
                if (vv > w0) { w3=w2;i3=i2; w2=w1;i2=i1; w1=w0;i1=i0; w0=vv;i0=d;}\
                else          { w3=w2;i3=i2; w2=w1;i2=i1; w1=vv;i1=d; }          \
            } else            { w3=w2;i3=i2; w2=vv;i2=d; }                       \
        } else                { w3=vv;i3=d; }                                    \
    }

__global__ void __launch_bounds__(64, 6)
autocorr_kernel(const float* __restrict__ gq,
                const float* __restrict__ gk,
                const float* __restrict__ gv,
                float* __restrict__ outV,
                float* __restrict__ outC) {
    __shared__ float2 Tk[2][32][STR2];
    __shared__ float2 Tq[2][32][STR2];

    const int w    = threadIdx.x >> 5;
    const int lane = threadIdx.x & 31;
    float2 (*K2)[STR2] = Tk[w];
    float2 (*Q2)[STR2] = Tq[w];
    float*  Kf = (float*)&K2[0][0];
    float*  Qf = (float*)&Q2[0][0];

    const long long r0  = ((long long)blockIdx.x * 2 + w) * 32;  // 32 rows/warp
    const long long off = r0 * 64;

    // stage 32 rows x 64 floats into a float2[32][33] tile (coalesced LDG,
    // conflict-free STS: bank (2*(it>>1)+lane)%32 distinct per lane)
#define STAGE(dstf, gsrc)                                                    \
    _Pragma("unroll")                                                        \
    for (int it = 0; it < 64; it++) {                                        \
        dstf[(it >> 1) * (2 * STR2) + ((it & 1) << 5) + lane]                \
            = gsrc[off + it * 32 + lane];                                    \
    }

    // ---- k, q staged ----
    STAGE(Kf, gk);
    STAGE(Qf, gq);
    __syncwarp();

    // ---- aligned packed k: kE[t] = (k[2t], k[2t+1]) ----
    unsigned long long kE[32];
    #pragma unroll
    for (int t = 0; t < 32; t++)
        kE[t] = *(const unsigned long long*)&K2[lane][t];

    // ---- top-4 state ----
    float w0=-CUDART_INF_F, w1=-CUDART_INF_F, w2=-CUDART_INF_F, w3=-CUDART_INF_F;
    int   i0=0, i1=0, i2=0, i3=0;

    // corr^T: rows of this warp share (b,h); l = l0 + lane
    const int b = (int)(r0 >> 14);
    const int h = ((int)(r0 >> 11)) & 7;
    const int l = ((int)(r0 & 2047)) + lane;
    float* cA = outC + (long long)b * (64 * 8 * 2048) + (long long)h * 2048 + l;

    // ---- EVEN d: two passes of 16 packed accumulators ----
    #pragma unroll
    for (int p = 0; p < 2; p++) {
        unsigned long long c2[16];
        #pragma unroll
        for (int dd = 0; dd < 16; dd++) c2[dd] = 0ull;

        #pragma unroll
        for (int m = 0; m < 32; m++) {
            unsigned long long q2 = *(const unsigned long long*)&Q2[lane][m];
            #pragma unroll
            for (int dd = 0; dd < 16; dd++)
                FMA2(c2[dd], q2, kE[(m + 32 - p * 16 - dd) & 31]);
        }
        #pragma unroll
        for (int dd = 0; dd < 16; dd++) {
            const int d = 2 * (p * 16 + dd);
            float lo, hi; UNPACK2(lo, hi, c2[dd]);
            const float v = lo + hi;
            cA[d * 16384] = v;
            TOPK_INS(v, d);
        }
    }

    // ---- misaligned packed k: kO[t] = (k[2t+1], k[(2t+2)&63]) ----
    unsigned long long kO[32];
    #pragma unroll
    for (int t = 0; t < 32; t++)
        PACK2(kO[t], Kf[lane * (2 * STR2) + 2 * t + 1],
                     Kf[lane * (2 * STR2) + ((2 * t + 2) & 63)]);

    // ---- ODD d ----
    #pragma unroll
    for (int p = 0; p < 2; p++) {
        unsigned long long c2[16];
        #pragma unroll
        for (int dd = 0; dd < 16; dd++) c2[dd] = 0ull;

        #pragma unroll
        for (int m = 0; m < 32; m++) {
            unsigned long long q2 = *(const unsigned long long*)&Q2[lane][m];
            #pragma unroll
            for (int dd = 0; dd < 16; dd++)
                FMA2(c2[dd], q2, kO[(m + 32 - p * 16 - dd - 1) & 31]);
        }
        #pragma unroll
        for (int dd = 0; dd < 16; dd++) {
            const int d = 2 * (p * 16 + dd) + 1;
            float lo, hi; UNPACK2(lo, hi, c2[dd]);
            const float v = lo + hi;
            cA[d * 16384] = v;
            TOPK_INS(v, d);
        }
    }

    // ---- softmax over the 4 weights (w0 is the max) ----
    const float e1 = __expf(w1 - w0), e2 = __expf(w2 - w0), e3 = __expf(w3 - w0);
    const float inv = 1.f / (1.f + e1 + e2 + e3);
    const float t0 = inv, t1 = e1 * inv, t2 = e2 * inv, t3 = e3 * inv;

    // ---- v staged into the (dead) k tile ----
    __syncwarp();
    STAGE(Kf, gv);
    __syncwarp();

    // ---- gather + direct V store (float4; L2 merges the half-sectors) ----
    {
        const float* vp = Kf + lane * (2 * STR2);
        float* outR = outV + off + lane * 64;
        #pragma unroll
        for (int eg = 0; eg < 16; eg++) {
            float4 o;
            #pragma unroll
            for (int s = 0; s < 4; s++) {
                const int e = eg * 4 + s;
                float sa =      t0 * vp[(e + i0) & 63];
                sa = fmaf(t1, vp[(e + i1) & 63], sa);
                sa = fmaf(t2, vp[(e + i2) & 63], sa);
                sa = fmaf(t3, vp[(e + i3) & 63], sa);
                (&o.x)[s] = sa;
            }
            *(float4*)(outR + eg * 4) = o;
        }
    }
}

extern "C" void kernel_launch(void* const* d_in, const int* in_sizes, int n_in,
                              void* d_out, int out_size) {
    const float* q = (const float*)d_in[0];
    const float* k = (const float*)d_in[1];
    const float* v = (const float*)d_in[2];
    float* outV = (float*)d_out;
    float* outC = (float*)d_out + (long long)32 * 8 * 2048 * 64;

    const int rows    = 32 * 8 * 2048;      // 524288
    const int nblocks = rows / 64;          // 8192 blocks, 2 warps (64 rows) each
    autocorr_kernel<<<nblocks, 64>>>(q, k, v, outV, outC);
}